// round 1
// baseline (speedup 1.0000x reference)
#include <cuda_runtime.h>
#include <cuda_bf16.h>
#include <cstddef>

// ---------------------------------------------------------------------------
// SupervisedTEMTransition on GB300 (sm_103a), round 1: correct + solid fp32.
//
// Pipeline (3 launches, all graph-capturable, no allocations):
//   1) bin_kernel      : single block; bins batch rows by action -> d_perm/d_off
//   2) trans_kernel    : per-(action, module) tiled SGEMM computing
//                        g_next = clip(g + D_a^T-routed delta, -1, 1)
//                        writes to device scratch + d_out tail region
//   3) cls_kernel      : 128x128x8 tiled SGEMM: logits = g_next @ W^T + b
// ---------------------------------------------------------------------------

#define BATCH_MAX   16384
#define G_TOTAL     768
#define NUM_STATES  4096
#define N_ACTIONS   4

__device__ int   d_perm[BATCH_MAX];
__device__ int   d_off[N_ACTIONS + 1];
__device__ float d_gnext[(size_t)BATCH_MAX * G_TOTAL];   // scratch for g_next

// ---------------------------------------------------------------------------
// Kernel 1: bin rows by action. Single block. Deterministic outputs downstream
// (accumulation order per row is independent of perm slot).
// ---------------------------------------------------------------------------
__global__ void bin_kernel(const int* __restrict__ act, int B) {
    __shared__ int cnt[N_ACTIONS];
    __shared__ int base[N_ACTIONS];
    int t = threadIdx.x;
    if (t < N_ACTIONS) cnt[t] = 0;
    __syncthreads();
    for (int b = t; b < B; b += blockDim.x) atomicAdd(&cnt[act[b]], 1);
    __syncthreads();
    if (t == 0) {
        int s = 0;
        for (int a = 0; a < N_ACTIONS; a++) { base[a] = s; d_off[a] = s; s += cnt[a]; }
        d_off[N_ACTIONS] = s;
    }
    __syncthreads();
    if (t < N_ACTIONS) cnt[t] = 0;
    __syncthreads();
    for (int b = t; b < B; b += blockDim.x) {
        int a = act[b];
        int p = base[a] + atomicAdd(&cnt[a], 1);
        d_perm[p] = b;
    }
}

// ---------------------------------------------------------------------------
// Kernel 2: routed transition. grid = (jtile<=4, rowtile=256, a*4+f=16).
// BM=BN=64, BK=16, 256 threads, 4x4 micro-tile per thread.
// delta[m][j] = sum_i g[m][i] * D_f[a][j][i];  out = clip(g + delta, -1, 1)
// ---------------------------------------------------------------------------
__global__ __launch_bounds__(256)
void trans_kernel(const float* __restrict__ emb,
                  const int*   __restrict__ state,
                  const float* __restrict__ D0, const float* __restrict__ D1,
                  const float* __restrict__ D2, const float* __restrict__ D3,
                  float* __restrict__ gdst,      // scratch [B,768]
                  float* __restrict__ gout,      // d_out tail [B,768] (may be null)
                  int B)
{
    __shared__ float Gs[16][68];
    __shared__ float Ds[16][68];
    __shared__ int   srow[64];   // state[b]*768 or -1
    __shared__ int   sb[64];     // original batch index or -1

    const int a = blockIdx.z >> 2;
    const int f = blockIdx.z & 3;
    const int nf   = (f < 2) ? 256 : 128;
    const int moff = (f == 0) ? 0 : (f == 1) ? 256 : (f == 2) ? 512 : 640;
    const int j0 = blockIdx.x * 64;
    if (j0 >= nf) return;
    const int start = d_off[a];
    const int cnt   = d_off[a + 1] - start;
    const int r0 = blockIdx.y * 64;
    if (r0 >= cnt) return;

    const float* Dbank = (f == 0) ? D0 : (f == 1) ? D1 : (f == 2) ? D2 : D3;
    const float* Dm = Dbank + (size_t)a * nf * nf;

    const int tid = threadIdx.x;
    if (tid < 64) {
        int rr = r0 + tid;
        if (rr < cnt) {
            int bidx = d_perm[start + rr];
            sb[tid]   = bidx;
            srow[tid] = state[bidx] * G_TOTAL;
        } else {
            sb[tid] = -1; srow[tid] = -1;
        }
    }
    __syncthreads();

    const int lm  = tid >> 2;          // 0..63
    const int lk4 = (tid & 3) * 4;     // 0,4,8,12
    const int tr  = tid >> 4;          // 0..15
    const int tc  = tid & 15;          // 0..15

    float acc[4][4] = {};

    for (int k0 = 0; k0 < nf; k0 += 16) {
        float4 gv = make_float4(0.f, 0.f, 0.f, 0.f);
        int sr = srow[lm];
        if (sr >= 0)
            gv = *(const float4*)(emb + sr + moff + k0 + lk4);
        float4 dv = *(const float4*)(Dm + (size_t)(j0 + lm) * nf + k0 + lk4);

        Gs[lk4 + 0][lm] = gv.x; Gs[lk4 + 1][lm] = gv.y;
        Gs[lk4 + 2][lm] = gv.z; Gs[lk4 + 3][lm] = gv.w;
        Ds[lk4 + 0][lm] = dv.x; Ds[lk4 + 1][lm] = dv.y;
        Ds[lk4 + 2][lm] = dv.z; Ds[lk4 + 3][lm] = dv.w;
        __syncthreads();

        #pragma unroll
        for (int k = 0; k < 16; k++) {
            float4 av = *(const float4*)&Gs[k][tr * 4];
            float4 bv = *(const float4*)&Ds[k][tc * 4];
            float ar[4] = {av.x, av.y, av.z, av.w};
            float br[4] = {bv.x, bv.y, bv.z, bv.w};
            #pragma unroll
            for (int i = 0; i < 4; i++)
                #pragma unroll
                for (int j = 0; j < 4; j++)
                    acc[i][j] = fmaf(ar[i], br[j], acc[i][j]);
        }
        __syncthreads();
    }

    // Epilogue: g_next = clip(g + delta, -1, 1)
    #pragma unroll
    for (int i = 0; i < 4; i++) {
        int m = tr * 4 + i;
        int bidx = sb[m];
        if (bidx < 0) continue;
        const float* grow = emb + srow[m] + moff + j0 + tc * 4;
        size_t obase = (size_t)bidx * G_TOTAL + moff + j0 + tc * 4;
        #pragma unroll
        for (int j = 0; j < 4; j++) {
            float v = grow[j] + acc[i][j];
            v = fminf(fmaxf(v, -1.0f), 1.0f);
            gdst[obase + j] = v;
            if (gout) gout[obase + j] = v;
        }
    }
}

// ---------------------------------------------------------------------------
// Kernel 3: classifier SGEMM. C[B,4096] = A[B,768] @ W[4096,768]^T + bias.
// 128x128 tile, BK=8, 256 threads, 8x8 micro-tile.
// ---------------------------------------------------------------------------
__global__ __launch_bounds__(256)
void cls_kernel(const float* __restrict__ A,
                const float* __restrict__ W,
                const float* __restrict__ bias,
                float* __restrict__ C)
{
    __shared__ float As[8][132];
    __shared__ float Bs[8][132];

    const int tid = threadIdx.x;
    const int m0 = blockIdx.y * 128;
    const int n0 = blockIdx.x * 128;

    const int lm  = tid >> 1;          // 0..127
    const int lk4 = (tid & 1) * 4;     // 0 or 4
    const int tr  = tid >> 4;          // 0..15
    const int tc  = tid & 15;          // 0..15

    const float* Ag = A + (size_t)(m0 + lm) * G_TOTAL + lk4;
    const float* Wg = W + (size_t)(n0 + lm) * G_TOTAL + lk4;

    float acc[8][8] = {};

    for (int k0 = 0; k0 < G_TOTAL; k0 += 8) {
        float4 av = *(const float4*)(Ag + k0);
        float4 wv = *(const float4*)(Wg + k0);
        As[lk4 + 0][lm] = av.x; As[lk4 + 1][lm] = av.y;
        As[lk4 + 2][lm] = av.z; As[lk4 + 3][lm] = av.w;
        Bs[lk4 + 0][lm] = wv.x; Bs[lk4 + 1][lm] = wv.y;
        Bs[lk4 + 2][lm] = wv.z; Bs[lk4 + 3][lm] = wv.w;
        __syncthreads();

        #pragma unroll
        for (int k = 0; k < 8; k++) {
            float ar[8], br[8];
            *(float4*)&ar[0] = *(const float4*)&As[k][tr * 8];
            *(float4*)&ar[4] = *(const float4*)&As[k][tr * 8 + 4];
            *(float4*)&br[0] = *(const float4*)&Bs[k][tc * 8];
            *(float4*)&br[4] = *(const float4*)&Bs[k][tc * 8 + 4];
            #pragma unroll
            for (int i = 0; i < 8; i++)
                #pragma unroll
                for (int j = 0; j < 8; j++)
                    acc[i][j] = fmaf(ar[i], br[j], acc[i][j]);
        }
        __syncthreads();
    }

    float bj[8];
    #pragma unroll
    for (int j = 0; j < 8; j++) bj[j] = bias[n0 + tc * 8 + j];

    #pragma unroll
    for (int i = 0; i < 8; i++) {
        size_t row = (size_t)(m0 + tr * 8 + i) * NUM_STATES + n0 + tc * 8;
        float4 o0, o1;
        o0.x = acc[i][0] + bj[0]; o0.y = acc[i][1] + bj[1];
        o0.z = acc[i][2] + bj[2]; o0.w = acc[i][3] + bj[3];
        o1.x = acc[i][4] + bj[4]; o1.y = acc[i][5] + bj[5];
        o1.z = acc[i][6] + bj[6]; o1.w = acc[i][7] + bj[7];
        *(float4*)&C[row]     = o0;
        *(float4*)&C[row + 4] = o1;
    }
}

// ---------------------------------------------------------------------------
// Launch
// ---------------------------------------------------------------------------
extern "C" void kernel_launch(void* const* d_in, const int* in_sizes, int n_in,
                              void* d_out, int out_size)
{
    const int*   state = (const int*)d_in[0];
    const int*   act   = (const int*)d_in[1];
    const float* emb   = (const float*)d_in[2];

    const float *D0, *D1, *D2, *D3, *W, *bias;
    // Disambiguate input ordering: dict order (emb,W,b,D0..D3) vs
    // signature order (emb,D0..D3,W,b) via in_sizes[3].
    if (in_sizes[3] == NUM_STATES * G_TOTAL) {
        W  = (const float*)d_in[3];
        bias = (const float*)d_in[4];
        D0 = (const float*)d_in[5];
        D1 = (const float*)d_in[6];
        D2 = (const float*)d_in[7];
        D3 = (const float*)d_in[8];
    } else {
        D0 = (const float*)d_in[3];
        D1 = (const float*)d_in[4];
        D2 = (const float*)d_in[5];
        D3 = (const float*)d_in[6];
        W  = (const float*)d_in[7];
        bias = (const float*)d_in[8];
    }

    const int B = in_sizes[0];
    float* out = (float*)d_out;

    float* logits = out;                             // [B, 4096]
    float* gout = nullptr;                           // [B, 768] tail, if present
    if ((size_t)out_size >= (size_t)B * (NUM_STATES + G_TOTAL))
        gout = out + (size_t)B * NUM_STATES;

    // Resolve device-scratch addresses (no allocation; __device__ globals).
    float* gnext_ptr = nullptr;
    cudaGetSymbolAddress((void**)&gnext_ptr, d_gnext);

    // 1) bin rows by action
    bin_kernel<<<1, 1024>>>(act, B);

    // 2) routed transition -> g_next (scratch + optional d_out tail)
    {
        dim3 grid(4, (B + 63) / 64, 16);
        trans_kernel<<<grid, 256>>>(emb, state, D0, D1, D2, D3,
                                    gnext_ptr, gout, B);
    }

    // 3) classifier GEMM -> logits
    {
        dim3 grid(NUM_STATES / 128, B / 128);
        cls_kernel<<<grid, 256>>>(gnext_ptr, W, bias, logits);
    }
}

// round 3
// speedup vs baseline: 3.0635x; 3.0635x over previous
#include <cuda_runtime.h>
#include <cuda_bf16.h>
#include <cstdint>
#include <cstddef>

// ---------------------------------------------------------------------------
// SupervisedTEMTransition on GB300 (sm_103a), round 3.
//
// The harness toolchain targets plain sm_103 (no 'a'), so tcgen05/TMEM are
// unavailable. Tensor path used instead: portable mma.sync.m16n8k8 tf32
// (legacy HMMA on Blackwell) with a cp.async 3-stage pipeline.
//
// Pipeline:
//   1) bin_kernel    : bin batch rows by action
//   2) trans_kernel  : fp32-exact routed transition; writes exact g_next to
//                      d_out tail and tf32-rounded copy to scratch (GEMM A)
//   3) wround_kernel : tf32-round W_cls into scratch (GEMM B)
//   4) cls_mma_kernel: C[16384,4096] = A[16384,768] @ W[4096,768]^T + b
//                      128x256 CTA tile, 8 warps x (64x64), tf32 mma.sync
// ---------------------------------------------------------------------------

#define BATCH_MAX   16384
#define G_TOTAL     768
#define NUM_STATES  4096
#define N_ACTIONS   4

__device__ int   d_perm[BATCH_MAX];
__device__ int   d_off[N_ACTIONS + 1];
__device__ float d_gnext[(size_t)BATCH_MAX * G_TOTAL];       // tf32-rounded A
__device__ float d_wtf32[(size_t)NUM_STATES * G_TOTAL];      // tf32-rounded W

__device__ __forceinline__ uint32_t smem_u32(const void* p) {
    uint32_t a;
    asm("{ .reg .u64 t; cvta.to.shared.u64 t, %1; cvt.u32.u64 %0, t; }"
        : "=r"(a) : "l"(p));
    return a;
}

__device__ __forceinline__ float tf32_rna(float x) {
    float r;
    asm("cvt.rna.tf32.f32 %0, %1;" : "=f"(r) : "f"(x));
    return r;
}

// ---------------------------------------------------------------------------
// Kernel 1: bin rows by action
// ---------------------------------------------------------------------------
__global__ void bin_kernel(const int* __restrict__ act, int B) {
    __shared__ int cnt[N_ACTIONS];
    __shared__ int base[N_ACTIONS];
    int t = threadIdx.x;
    if (t < N_ACTIONS) cnt[t] = 0;
    __syncthreads();
    for (int b = t; b < B; b += blockDim.x) atomicAdd(&cnt[act[b]], 1);
    __syncthreads();
    if (t == 0) {
        int s = 0;
        for (int a = 0; a < N_ACTIONS; a++) { base[a] = s; d_off[a] = s; s += cnt[a]; }
        d_off[N_ACTIONS] = s;
    }
    __syncthreads();
    if (t < N_ACTIONS) cnt[t] = 0;
    __syncthreads();
    for (int b = t; b < B; b += blockDim.x) {
        int a = act[b];
        int p = base[a] + atomicAdd(&cnt[a], 1);
        d_perm[p] = b;
    }
}

// ---------------------------------------------------------------------------
// Kernel 2: routed transition (fp32-exact math; dual-write epilogue)
// ---------------------------------------------------------------------------
__global__ __launch_bounds__(256)
void trans_kernel(const float* __restrict__ emb,
                  const int*   __restrict__ state,
                  const float* __restrict__ D0, const float* __restrict__ D1,
                  const float* __restrict__ D2, const float* __restrict__ D3,
                  float* __restrict__ gdst,      // tf32-rounded scratch
                  float* __restrict__ gout,      // exact fp32 d_out tail
                  int B)
{
    __shared__ float Gs[16][68];
    __shared__ float Ds[16][68];
    __shared__ int   srow[64];
    __shared__ int   sb[64];

    const int a = blockIdx.z >> 2;
    const int f = blockIdx.z & 3;
    const int nf   = (f < 2) ? 256 : 128;
    const int moff = (f == 0) ? 0 : (f == 1) ? 256 : (f == 2) ? 512 : 640;
    const int j0 = blockIdx.x * 64;
    if (j0 >= nf) return;
    const int start = d_off[a];
    const int cnt   = d_off[a + 1] - start;
    const int r0 = blockIdx.y * 64;
    if (r0 >= cnt) return;

    const float* Dbank = (f == 0) ? D0 : (f == 1) ? D1 : (f == 2) ? D2 : D3;
    const float* Dm = Dbank + (size_t)a * nf * nf;

    const int tid = threadIdx.x;
    if (tid < 64) {
        int rr = r0 + tid;
        if (rr < cnt) {
            int bidx = d_perm[start + rr];
            sb[tid]   = bidx;
            srow[tid] = state[bidx] * G_TOTAL;
        } else {
            sb[tid] = -1; srow[tid] = -1;
        }
    }
    __syncthreads();

    const int lm  = tid >> 2;
    const int lk4 = (tid & 3) * 4;
    const int tr  = tid >> 4;
    const int tc  = tid & 15;

    float acc[4][4] = {};

    for (int k0 = 0; k0 < nf; k0 += 16) {
        float4 gv = make_float4(0.f, 0.f, 0.f, 0.f);
        int sr = srow[lm];
        if (sr >= 0)
            gv = *(const float4*)(emb + sr + moff + k0 + lk4);
        float4 dv = *(const float4*)(Dm + (size_t)(j0 + lm) * nf + k0 + lk4);

        Gs[lk4 + 0][lm] = gv.x; Gs[lk4 + 1][lm] = gv.y;
        Gs[lk4 + 2][lm] = gv.z; Gs[lk4 + 3][lm] = gv.w;
        Ds[lk4 + 0][lm] = dv.x; Ds[lk4 + 1][lm] = dv.y;
        Ds[lk4 + 2][lm] = dv.z; Ds[lk4 + 3][lm] = dv.w;
        __syncthreads();

        #pragma unroll
        for (int k = 0; k < 16; k++) {
            float4 av = *(const float4*)&Gs[k][tr * 4];
            float4 bv = *(const float4*)&Ds[k][tc * 4];
            float ar[4] = {av.x, av.y, av.z, av.w};
            float br[4] = {bv.x, bv.y, bv.z, bv.w};
            #pragma unroll
            for (int i = 0; i < 4; i++)
                #pragma unroll
                for (int j = 0; j < 4; j++)
                    acc[i][j] = fmaf(ar[i], br[j], acc[i][j]);
        }
        __syncthreads();
    }

    #pragma unroll
    for (int i = 0; i < 4; i++) {
        int m = tr * 4 + i;
        int bidx = sb[m];
        if (bidx < 0) continue;
        const float* grow = emb + srow[m] + moff + j0 + tc * 4;
        size_t obase = (size_t)bidx * G_TOTAL + moff + j0 + tc * 4;
        #pragma unroll
        for (int j = 0; j < 4; j++) {
            float v = grow[j] + acc[i][j];
            v = fminf(fmaxf(v, -1.0f), 1.0f);
            gdst[obase + j] = tf32_rna(v);     // rounded copy for tensor GEMM
            if (gout) gout[obase + j] = v;     // exact copy for output
        }
    }
}

// ---------------------------------------------------------------------------
// Kernel 3: tf32-round W (one float4 per thread)
// ---------------------------------------------------------------------------
__global__ __launch_bounds__(256)
void wround_kernel(const float* __restrict__ W, float* __restrict__ Wo) {
    int i = (blockIdx.x * 256 + threadIdx.x) * 4;
    float4 v = *(const float4*)(W + i);
    v.x = tf32_rna(v.x); v.y = tf32_rna(v.y);
    v.z = tf32_rna(v.z); v.w = tf32_rna(v.w);
    *(float4*)(Wo + i) = v;
}

// ---------------------------------------------------------------------------
// Kernel 4: tf32 mma.sync classifier GEMM.
//   CTA tile 128(M) x 256(N), K chunks of 32. 8 warps, warp tile 64x64.
//   3-stage cp.async pipeline. m16n8k8 tf32 fragments.
// ---------------------------------------------------------------------------
#define AKP          36                       // padded row length (floats)
#define STAGE_FLOATS (128 * AKP + 256 * AKP)  // A (4608) + B (9216) = 13824
#define A_FLOATS     (128 * AKP)
#define STAGES       3
#define CHUNKS       24
#define CLS_DYN_SMEM (STAGES * STAGE_FLOATS * 4)

extern __shared__ float cls_sm[];

__device__ __forceinline__ void cp16(uint32_t saddr, const float* g) {
    asm volatile("cp.async.cg.shared.global [%0], [%1], 16;"
                 :: "r"(saddr), "l"(g) : "memory");
}

__global__ __launch_bounds__(256, 1)
void cls_mma_kernel(const float* __restrict__ A,     // [16384,768] tf32-rounded
                    const float* __restrict__ W,     // [4096,768] tf32-rounded
                    const float* __restrict__ bias,
                    float* __restrict__ C)
{
    __shared__ float bias_s[256];

    const int tid = threadIdx.x;
    const int n0 = blockIdx.x * 256;
    const int m0 = blockIdx.y * 128;

    bias_s[tid] = bias[n0 + tid];

    const int lane = tid & 31;
    const int wid  = tid >> 5;
    const int g    = lane >> 2;       // groupID 0..7
    const int tg   = lane & 3;        // threadID_in_group 0..3
    const int wm   = (wid >> 2) * 64; // warp M offset 0/64
    const int wn   = (wid & 3) * 64;  // warp N offset 0..192

    // per-thread cp.async map: 12 x 16B per chunk (4 for A, 8 for B)
    const float* gp[12];
    uint32_t soff[12];                // float offsets within a stage
    #pragma unroll
    for (int i = 0; i < 12; i++) {
        if (i < 4) {
            int u = tid + i * 256;                    // 0..1023
            int r = u >> 3, c = u & 7;
            gp[i]   = A + (size_t)(m0 + r) * G_TOTAL + c * 4;
            soff[i] = r * AKP + c * 4;
        } else {
            int u = tid + (i - 4) * 256;              // 0..2047
            int r = u >> 3, c = u & 7;
            gp[i]   = W + (size_t)(n0 + r) * G_TOTAL + c * 4;
            soff[i] = A_FLOATS + r * AKP + c * 4;
        }
    }

    const uint32_t sbase = smem_u32(cls_sm);

    // prologue: issue chunks 0..2
    #pragma unroll
    for (int c = 0; c < STAGES; c++) {
        uint32_t st = sbase + (c % STAGES) * STAGE_FLOATS * 4;
        #pragma unroll
        for (int i = 0; i < 12; i++)
            cp16(st + soff[i] * 4, gp[i] + c * 32);
        asm volatile("cp.async.commit_group;" ::: "memory");
    }

    float acc[4][8][4] = {};

    for (int c = 0; c < CHUNKS; c++) {
        if (c < CHUNKS - 2)
            asm volatile("cp.async.wait_group 2;" ::: "memory");
        else if (c == CHUNKS - 2)
            asm volatile("cp.async.wait_group 1;" ::: "memory");
        else
            asm volatile("cp.async.wait_group 0;" ::: "memory");
        __syncthreads();

        const float* sAp = cls_sm + (c % STAGES) * STAGE_FLOATS;
        const float* sBp = sAp + A_FLOATS;

        #pragma unroll
        for (int ks = 0; ks < 4; ks++) {
            uint32_t a[4][4];
            #pragma unroll
            for (int mt = 0; mt < 4; mt++) {
                const uint32_t* ap = (const uint32_t*)(sAp + (wm + mt * 16 + g) * AKP + ks * 8 + tg);
                a[mt][0] = ap[0];
                a[mt][1] = ap[8 * AKP];
                a[mt][2] = ap[4];
                a[mt][3] = ap[8 * AKP + 4];
            }
            uint32_t b[8][2];
            #pragma unroll
            for (int nt = 0; nt < 8; nt++) {
                const uint32_t* bp = (const uint32_t*)(sBp + (wn + nt * 8 + g) * AKP + ks * 8 + tg);
                b[nt][0] = bp[0];
                b[nt][1] = bp[4];
            }
            #pragma unroll
            for (int mt = 0; mt < 4; mt++)
                #pragma unroll
                for (int nt = 0; nt < 8; nt++) {
                    asm volatile(
                        "mma.sync.aligned.m16n8k8.row.col.f32.tf32.tf32.f32 "
                        "{%0,%1,%2,%3}, {%4,%5,%6,%7}, {%8,%9}, {%0,%1,%2,%3};"
                        : "+f"(acc[mt][nt][0]), "+f"(acc[mt][nt][1]),
                          "+f"(acc[mt][nt][2]), "+f"(acc[mt][nt][3])
                        : "r"(a[mt][0]), "r"(a[mt][1]), "r"(a[mt][2]), "r"(a[mt][3]),
                          "r"(b[nt][0]), "r"(b[nt][1]));
                }
        }
        __syncthreads();

        if (c + STAGES < CHUNKS) {
            uint32_t st = sbase + (c % STAGES) * STAGE_FLOATS * 4;
            #pragma unroll
            for (int i = 0; i < 12; i++)
                cp16(st + soff[i] * 4, gp[i] + (c + STAGES) * 32);
            asm volatile("cp.async.commit_group;" ::: "memory");
        }
    }

    // epilogue: bias + store. c0/c1 -> (row g, cols 2tg,2tg+1); c2/c3 -> row g+8
    #pragma unroll
    for (int mt = 0; mt < 4; mt++) {
        int r_lo = m0 + wm + mt * 16 + g;
        float* C0 = C + (size_t)r_lo * NUM_STATES + n0;
        float* C1 = C + (size_t)(r_lo + 8) * NUM_STATES + n0;
        #pragma unroll
        for (int nt = 0; nt < 8; nt++) {
            int nc = wn + nt * 8 + tg * 2;
            float b0 = bias_s[nc], b1 = bias_s[nc + 1];
            float2 lo = make_float2(acc[mt][nt][0] + b0, acc[mt][nt][1] + b1);
            float2 hi = make_float2(acc[mt][nt][2] + b0, acc[mt][nt][3] + b1);
            *(float2*)(C0 + nc) = lo;
            *(float2*)(C1 + nc) = hi;
        }
    }
}

// ---------------------------------------------------------------------------
// Launch
// ---------------------------------------------------------------------------
extern "C" void kernel_launch(void* const* d_in, const int* in_sizes, int n_in,
                              void* d_out, int out_size)
{
    const int*   state = (const int*)d_in[0];
    const int*   act   = (const int*)d_in[1];
    const float* emb   = (const float*)d_in[2];

    const float *D0, *D1, *D2, *D3, *W, *bias;
    if (in_sizes[3] == NUM_STATES * G_TOTAL) {
        W  = (const float*)d_in[3];
        bias = (const float*)d_in[4];
        D0 = (const float*)d_in[5];
        D1 = (const float*)d_in[6];
        D2 = (const float*)d_in[7];
        D3 = (const float*)d_in[8];
    } else {
        D0 = (const float*)d_in[3];
        D1 = (const float*)d_in[4];
        D2 = (const float*)d_in[5];
        D3 = (const float*)d_in[6];
        W  = (const float*)d_in[7];
        bias = (const float*)d_in[8];
    }

    const int B = in_sizes[0];
    float* out = (float*)d_out;

    float* logits = out;
    float* gout = nullptr;
    if ((size_t)out_size >= (size_t)B * (NUM_STATES + G_TOTAL))
        gout = out + (size_t)B * NUM_STATES;

    float* gnext_ptr = nullptr;
    float* wtf_ptr = nullptr;
    cudaGetSymbolAddress((void**)&gnext_ptr, d_gnext);
    cudaGetSymbolAddress((void**)&wtf_ptr, d_wtf32);

    cudaFuncSetAttribute(cls_mma_kernel,
                         cudaFuncAttributeMaxDynamicSharedMemorySize, CLS_DYN_SMEM);

    // 1) bin rows by action
    bin_kernel<<<1, 1024>>>(act, B);

    // 2) routed transition -> exact g_next (out tail) + tf32-rounded scratch
    {
        dim3 grid(4, (B + 63) / 64, 16);
        trans_kernel<<<grid, 256>>>(emb, state, D0, D1, D2, D3,
                                    gnext_ptr, gout, B);
    }

    // 3) tf32-round W
    wround_kernel<<<(NUM_STATES * G_TOTAL / 4) / 256, 256>>>(W, wtf_ptr);

    // 4) tf32 tensor-core classifier GEMM
    {
        dim3 grid(NUM_STATES / 256, B / 128);
        cls_mma_kernel<<<grid, 256, CLS_DYN_SMEM>>>(gnext_ptr, wtf_ptr, bias, logits);
    }
}

// round 5
// speedup vs baseline: 3.0650x; 1.0005x over previous
#include <cuda_runtime.h>
#include <cuda_bf16.h>
#include <cstdint>
#include <cstddef>

// ---------------------------------------------------------------------------
// SupervisedTEMTransition on GB300 (sm_103a), round 4.
//
// R3: cls_mma_kernel at tensor=55%, occ=12.4% (1 CTA/SM), 2 syncs/chunk.
// R4: cls rebuilt for 2 CTAs/SM latency hiding:
//   - CTA tile 128x128, 8 warps x (64x32) -> ~110 regs, __launch_bounds__(256,2)
//   - 3-stage cp.async ring with ONE __syncthreads per chunk (issue-at-top)
//   - SMEM 108KB/CTA so two CTAs co-reside (224KB/SM)
// bin/trans/wround unchanged.
// ---------------------------------------------------------------------------

#define BATCH_MAX   16384
#define G_TOTAL     768
#define NUM_STATES  4096
#define N_ACTIONS   4

__device__ int   d_perm[BATCH_MAX];
__device__ int   d_off[N_ACTIONS + 1];
__device__ float d_gnext[(size_t)BATCH_MAX * G_TOTAL];       // tf32-rounded A
__device__ float d_wtf32[(size_t)NUM_STATES * G_TOTAL];      // tf32-rounded W

__device__ __forceinline__ uint32_t smem_u32(const void* p) {
    uint32_t a;
    asm("{ .reg .u64 t; cvta.to.shared.u64 t, %1; cvt.u32.u64 %0, t; }"
        : "=r"(a) : "l"(p));
    return a;
}

__device__ __forceinline__ float tf32_rna(float x) {
    float r;
    asm("cvt.rna.tf32.f32 %0, %1;" : "=f"(r) : "f"(x));
    return r;
}

// ---------------------------------------------------------------------------
// Kernel 1: bin rows by action
// ---------------------------------------------------------------------------
__global__ void bin_kernel(const int* __restrict__ act, int B) {
    __shared__ int cnt[N_ACTIONS];
    __shared__ int base[N_ACTIONS];
    int t = threadIdx.x;
    if (t < N_ACTIONS) cnt[t] = 0;
    __syncthreads();
    for (int b = t; b < B; b += blockDim.x) atomicAdd(&cnt[act[b]], 1);
    __syncthreads();
    if (t == 0) {
        int s = 0;
        for (int a = 0; a < N_ACTIONS; a++) { base[a] = s; d_off[a] = s; s += cnt[a]; }
        d_off[N_ACTIONS] = s;
    }
    __syncthreads();
    if (t < N_ACTIONS) cnt[t] = 0;
    __syncthreads();
    for (int b = t; b < B; b += blockDim.x) {
        int a = act[b];
        int p = base[a] + atomicAdd(&cnt[a], 1);
        d_perm[p] = b;
    }
}

// ---------------------------------------------------------------------------
// Kernel 2: routed transition (fp32-exact math; dual-write epilogue)
// ---------------------------------------------------------------------------
__global__ __launch_bounds__(256)
void trans_kernel(const float* __restrict__ emb,
                  const int*   __restrict__ state,
                  const float* __restrict__ D0, const float* __restrict__ D1,
                  const float* __restrict__ D2, const float* __restrict__ D3,
                  float* __restrict__ gdst,      // tf32-rounded scratch
                  float* __restrict__ gout,      // exact fp32 d_out tail
                  int B)
{
    __shared__ float Gs[16][68];
    __shared__ float Ds[16][68];
    __shared__ int   srow[64];
    __shared__ int   sb[64];

    const int a = blockIdx.z >> 2;
    const int f = blockIdx.z & 3;
    const int nf   = (f < 2) ? 256 : 128;
    const int moff = (f == 0) ? 0 : (f == 1) ? 256 : (f == 2) ? 512 : 640;
    const int j0 = blockIdx.x * 64;
    if (j0 >= nf) return;
    const int start = d_off[a];
    const int cnt   = d_off[a + 1] - start;
    const int r0 = blockIdx.y * 64;
    if (r0 >= cnt) return;

    const float* Dbank = (f == 0) ? D0 : (f == 1) ? D1 : (f == 2) ? D2 : D3;
    const float* Dm = Dbank + (size_t)a * nf * nf;

    const int tid = threadIdx.x;
    if (tid < 64) {
        int rr = r0 + tid;
        if (rr < cnt) {
            int bidx = d_perm[start + rr];
            sb[tid]   = bidx;
            srow[tid] = state[bidx] * G_TOTAL;
        } else {
            sb[tid] = -1; srow[tid] = -1;
        }
    }
    __syncthreads();

    const int lm  = tid >> 2;
    const int lk4 = (tid & 3) * 4;
    const int tr  = tid >> 4;
    const int tc  = tid & 15;

    float acc[4][4] = {};

    for (int k0 = 0; k0 < nf; k0 += 16) {
        float4 gv = make_float4(0.f, 0.f, 0.f, 0.f);
        int sr = srow[lm];
        if (sr >= 0)
            gv = *(const float4*)(emb + sr + moff + k0 + lk4);
        float4 dv = *(const float4*)(Dm + (size_t)(j0 + lm) * nf + k0 + lk4);

        Gs[lk4 + 0][lm] = gv.x; Gs[lk4 + 1][lm] = gv.y;
        Gs[lk4 + 2][lm] = gv.z; Gs[lk4 + 3][lm] = gv.w;
        Ds[lk4 + 0][lm] = dv.x; Ds[lk4 + 1][lm] = dv.y;
        Ds[lk4 + 2][lm] = dv.z; Ds[lk4 + 3][lm] = dv.w;
        __syncthreads();

        #pragma unroll
        for (int k = 0; k < 16; k++) {
            float4 av = *(const float4*)&Gs[k][tr * 4];
            float4 bv = *(const float4*)&Ds[k][tc * 4];
            float ar[4] = {av.x, av.y, av.z, av.w};
            float br[4] = {bv.x, bv.y, bv.z, bv.w};
            #pragma unroll
            for (int i = 0; i < 4; i++)
                #pragma unroll
                for (int j = 0; j < 4; j++)
                    acc[i][j] = fmaf(ar[i], br[j], acc[i][j]);
        }
        __syncthreads();
    }

    #pragma unroll
    for (int i = 0; i < 4; i++) {
        int m = tr * 4 + i;
        int bidx = sb[m];
        if (bidx < 0) continue;
        const float* grow = emb + srow[m] + moff + j0 + tc * 4;
        size_t obase = (size_t)bidx * G_TOTAL + moff + j0 + tc * 4;
        #pragma unroll
        for (int j = 0; j < 4; j++) {
            float v = grow[j] + acc[i][j];
            v = fminf(fmaxf(v, -1.0f), 1.0f);
            gdst[obase + j] = tf32_rna(v);     // rounded copy for tensor GEMM
            if (gout) gout[obase + j] = v;     // exact copy for output
        }
    }
}

// ---------------------------------------------------------------------------
// Kernel 3: tf32-round W (one float4 per thread)
// ---------------------------------------------------------------------------
__global__ __launch_bounds__(256)
void wround_kernel(const float* __restrict__ W, float* __restrict__ Wo) {
    int i = (blockIdx.x * 256 + threadIdx.x) * 4;
    float4 v = *(const float4*)(W + i);
    v.x = tf32_rna(v.x); v.y = tf32_rna(v.y);
    v.z = tf32_rna(v.z); v.w = tf32_rna(v.w);
    *(float4*)(Wo + i) = v;
}

// ---------------------------------------------------------------------------
// Kernel 4: tf32 mma.sync classifier GEMM, 2 CTAs/SM.
//   CTA tile 128(M) x 128(N), K chunks of 32. 8 warps x (64x32) warp tiles.
//   3-stage cp.async ring, single __syncthreads per chunk (issue-at-top).
// ---------------------------------------------------------------------------
#define AKP          36                       // padded row length (floats)
#define A_FLOATS     (128 * AKP)              // 4608
#define STAGE_FLOATS (2 * 128 * AKP)          // A + B = 9216 floats (36864 B)
#define STAGES       3
#define CHUNKS       24
#define CLS_DYN_SMEM (STAGES * STAGE_FLOATS * 4)   // 110592 B

extern __shared__ float cls_sm[];

__device__ __forceinline__ void cp16(uint32_t saddr, const float* g) {
    asm volatile("cp.async.cg.shared.global [%0], [%1], 16;"
                 :: "r"(saddr), "l"(g) : "memory");
}

__global__ __launch_bounds__(256, 2)
void cls_mma_kernel(const float* __restrict__ A,     // [16384,768] tf32-rounded
                    const float* __restrict__ W,     // [4096,768] tf32-rounded
                    const float* __restrict__ bias,
                    float* __restrict__ C)
{
    __shared__ float bias_s[128];

    const int tid = threadIdx.x;
    const int n0 = blockIdx.x * 128;
    const int m0 = blockIdx.y * 128;

    if (tid < 128) bias_s[tid] = bias[n0 + tid];

    const int lane = tid & 31;
    const int wid  = tid >> 5;
    const int g    = lane >> 2;       // groupID 0..7
    const int tg   = lane & 3;        // threadID_in_group 0..3
    const int wm   = (wid >> 2) * 64; // warp M offset 0/64
    const int wn   = (wid & 3) * 32;  // warp N offset 0..96

    // cp.async map: each thread loads 4 A float4s + 4 B float4s per chunk.
    // unit i covers row (tid>>3)+32*i, 16B-col (tid&7).
    const int lrow = tid >> 3;        // 0..31
    const int lcol = tid & 7;         // 0..7
    const float* gA = A + (size_t)(m0 + lrow) * G_TOTAL + lcol * 4;
    const float* gB = W + (size_t)(n0 + lrow) * G_TOTAL + lcol * 4;
    const uint32_t sA0 = lrow * AKP + lcol * 4;            // floats
    const uint32_t sB0 = A_FLOATS + sA0;

    const uint32_t sbase = smem_u32(cls_sm);

    #define ISSUE_CHUNK(c)                                                     \
        do {                                                                   \
            uint32_t _st = sbase + ((c) % STAGES) * (STAGE_FLOATS * 4);        \
            _Pragma("unroll")                                                  \
            for (int i = 0; i < 4; i++)                                        \
                cp16(_st + (sA0 + i * 32 * AKP) * 4,                           \
                     gA + (size_t)i * 32 * G_TOTAL + (c) * 32);                \
            _Pragma("unroll")                                                  \
            for (int i = 0; i < 4; i++)                                        \
                cp16(_st + (sB0 + i * 32 * AKP) * 4,                           \
                     gB + (size_t)i * 32 * G_TOTAL + (c) * 32);                \
            asm volatile("cp.async.commit_group;" ::: "memory");               \
        } while (0)

    // prologue: chunks 0 and 1
    ISSUE_CHUNK(0);
    ISSUE_CHUNK(1);

    float acc[4][4][4] = {};

    for (int c = 0; c < CHUNKS; c++) {
        if (c < CHUNKS - 1)
            asm volatile("cp.async.wait_group 1;" ::: "memory");
        else
            asm volatile("cp.async.wait_group 0;" ::: "memory");
        __syncthreads();   // stage c ready; stage consumed at iter c-1 free

        if (c + 2 < CHUNKS)
            ISSUE_CHUNK(c + 2);

        const float* sAp = cls_sm + (c % STAGES) * STAGE_FLOATS;
        const float* sBp = sAp + A_FLOATS;

        #pragma unroll
        for (int ks = 0; ks < 4; ks++) {
            uint32_t a[4][4];
            #pragma unroll
            for (int mt = 0; mt < 4; mt++) {
                const uint32_t* ap =
                    (const uint32_t*)(sAp + (wm + mt * 16 + g) * AKP + ks * 8 + tg);
                a[mt][0] = ap[0];
                a[mt][1] = ap[8 * AKP];
                a[mt][2] = ap[4];
                a[mt][3] = ap[8 * AKP + 4];
            }
            uint32_t b[4][2];
            #pragma unroll
            for (int nt = 0; nt < 4; nt++) {
                const uint32_t* bp =
                    (const uint32_t*)(sBp + (wn + nt * 8 + g) * AKP + ks * 8 + tg);
                b[nt][0] = bp[0];
                b[nt][1] = bp[4];
            }
            #pragma unroll
            for (int mt = 0; mt < 4; mt++)
                #pragma unroll
                for (int nt = 0; nt < 4; nt++) {
                    asm volatile(
                        "mma.sync.aligned.m16n8k8.row.col.f32.tf32.tf32.f32 "
                        "{%0,%1,%2,%3}, {%4,%5,%6,%7}, {%8,%9}, {%0,%1,%2,%3};"
                        : "+f"(acc[mt][nt][0]), "+f"(acc[mt][nt][1]),
                          "+f"(acc[mt][nt][2]), "+f"(acc[mt][nt][3])
                        : "r"(a[mt][0]), "r"(a[mt][1]), "r"(a[mt][2]), "r"(a[mt][3]),
                          "r"(b[nt][0]), "r"(b[nt][1]));
                }
        }
    }
    #undef ISSUE_CHUNK

    // epilogue: bias + store
    #pragma unroll
    for (int mt = 0; mt < 4; mt++) {
        int r_lo = m0 + wm + mt * 16 + g;
        float* C0 = C + (size_t)r_lo * NUM_STATES + n0;
        float* C1 = C + (size_t)(r_lo + 8) * NUM_STATES + n0;
        #pragma unroll
        for (int nt = 0; nt < 4; nt++) {
            int nc = wn + nt * 8 + tg * 2;
            float b0 = bias_s[nc], b1 = bias_s[nc + 1];
            *(float2*)(C0 + nc) = make_float2(acc[mt][nt][0] + b0, acc[mt][nt][1] + b1);
            *(float2*)(C1 + nc) = make_float2(acc[mt][nt][2] + b0, acc[mt][nt][3] + b1);
        }
    }
}

// ---------------------------------------------------------------------------
// Launch
// ---------------------------------------------------------------------------
extern "C" void kernel_launch(void* const* d_in, const int* in_sizes, int n_in,
                              void* d_out, int out_size)
{
    const int*   state = (const int*)d_in[0];
    const int*   act   = (const int*)d_in[1];
    const float* emb   = (const float*)d_in[2];

    const float *D0, *D1, *D2, *D3, *W, *bias;
    if (in_sizes[3] == NUM_STATES * G_TOTAL) {
        W  = (const float*)d_in[3];
        bias = (const float*)d_in[4];
        D0 = (const float*)d_in[5];
        D1 = (const float*)d_in[6];
        D2 = (const float*)d_in[7];
        D3 = (const float*)d_in[8];
    } else {
        D0 = (const float*)d_in[3];
        D1 = (const float*)d_in[4];
        D2 = (const float*)d_in[5];
        D3 = (const float*)d_in[6];
        W  = (const float*)d_in[7];
        bias = (const float*)d_in[8];
    }

    const int B = in_sizes[0];
    float* out = (float*)d_out;

    float* logits = out;
    float* gout = nullptr;
    if ((size_t)out_size >= (size_t)B * (NUM_STATES + G_TOTAL))
        gout = out + (size_t)B * NUM_STATES;

    float* gnext_ptr = nullptr;
    float* wtf_ptr = nullptr;
    cudaGetSymbolAddress((void**)&gnext_ptr, d_gnext);
    cudaGetSymbolAddress((void**)&wtf_ptr, d_wtf32);

    cudaFuncSetAttribute(cls_mma_kernel,
                         cudaFuncAttributeMaxDynamicSharedMemorySize, CLS_DYN_SMEM);

    // 1) bin rows by action
    bin_kernel<<<1, 1024>>>(act, B);

    // 2) routed transition -> exact g_next (out tail) + tf32-rounded scratch
    {
        dim3 grid(4, (B + 63) / 64, 16);
        trans_kernel<<<grid, 256>>>(emb, state, D0, D1, D2, D3,
                                    gnext_ptr, gout, B);
    }

    // 3) tf32-round W
    wround_kernel<<<(NUM_STATES * G_TOTAL / 4) / 256, 256>>>(W, wtf_ptr);

    // 4) tf32 tensor-core classifier GEMM
    {
        dim3 grid(NUM_STATES / 128, B / 128);
        cls_mma_kernel<<<grid, 256, CLS_DYN_SMEM>>>(gnext_ptr, wtf_ptr, bias, logits);
    }
}